// round 4
// baseline (speedup 1.0000x reference)
#include <cuda_runtime.h>
#include <cstdint>

#define BATCH 256
#define NTOK  320
#define CDIM  768
#define LZ    64
#define LK    256
#define SCALE 0.125f

// Scratch: O transposed per batch, [b][c][t] -> flat equals Y[b] (64,768) row-major.
__device__ float g_OT[(size_t)BATCH * CDIM * LZ];

__device__ __forceinline__ uint32_t f2t(float x) {
    uint32_t r;
    asm("cvt.rna.tf32.f32 %0, %1;" : "=r"(r) : "f"(x));
    return r;
}

__device__ __forceinline__ void mma8(float* d,
                                     uint32_t a0, uint32_t a1, uint32_t a2, uint32_t a3,
                                     uint32_t b0, uint32_t b1) {
    asm volatile(
        "mma.sync.aligned.m16n8k8.row.col.f32.tf32.tf32.f32 "
        "{%0,%1,%2,%3}, {%4,%5,%6,%7}, {%8,%9}, {%0,%1,%2,%3};\n"
        : "+f"(d[0]), "+f"(d[1]), "+f"(d[2]), "+f"(d[3])
        : "r"(a0), "r"(a1), "r"(a2), "r"(a3), "r"(b0), "r"(b1));
}

__device__ __forceinline__ void ldsm4(uint32_t* r, uint32_t saddr) {
    asm volatile("ldmatrix.sync.aligned.m8n8.x4.shared.b16 {%0,%1,%2,%3}, [%4];"
                 : "=r"(r[0]), "=r"(r[1]), "=r"(r[2]), "=r"(r[3]) : "r"(saddr));
}

__device__ __forceinline__ void cpa16(uint32_t saddr, const void* gaddr) {
    asm volatile("cp.async.cg.shared.global [%0], [%1], 16;\n"
                 :: "r"(saddr), "l"(gaddr));
}
__device__ __forceinline__ void cpa_commit() {
    asm volatile("cp.async.commit_group;\n");
}
template <int N>
__device__ __forceinline__ void cpa_wait() {
    asm volatile("cp.async.wait_group %0;\n" :: "n"(N));
}

// ---------------- fused attention per batch (tf32 tensor cores, 512 threads) ----------------
#define P1_LD  36   // %32==4 -> ldsm rows on distinct bank groups
#define SS_LD  260  // %32==4
#define K2_LD  72   // %32==8 -> scalar B loads conflict-free
#define STG_LD 68

#define OFF_POOL (LZ * SS_LD)                 // 16640 words
// phase1 pool: Q0,Q1 (64x36), K0,K1 (256x36) = 23040 words
// phase2 pool: K2 (256x72)=18432, stage (64x68)=4352 -> 22784 words
#define SMEM_WORDS (OFF_POOL + 23040)         // 39680 words = 158720 B

extern __shared__ float smem[];

__global__ __launch_bounds__(512, 1) void attn_k(const float* __restrict__ x,
                                                 float* __restrict__ out) {
    float*    sS  = smem;                      // 64 x 260 f32 scores -> tf32 probs
    uint32_t* sSu = (uint32_t*)smem;
    uint32_t* pool = (uint32_t*)(smem + OFF_POOL);
    uint32_t* sQ[2] = { pool, pool + 2304 };
    uint32_t* sK[2] = { pool + 4608, pool + 4608 + 9216 };
    uint32_t* sK2   = pool;                    // phase 2
    float*    stage = (float*)(pool + 18432);  // phase 2

    const uint32_t ssb  = (uint32_t)__cvta_generic_to_shared(sS);
    const uint32_t sqb0 = (uint32_t)__cvta_generic_to_shared(sQ[0]);
    const uint32_t sqb1 = (uint32_t)__cvta_generic_to_shared(sQ[1]);
    const uint32_t skb0 = (uint32_t)__cvta_generic_to_shared(sK[0]);
    const uint32_t skb1 = (uint32_t)__cvta_generic_to_shared(sK[1]);

    const int b    = blockIdx.x;
    const int tid  = threadIdx.x;
    const int wid  = tid >> 5;
    const int lane = tid & 31;
    const int grp  = lane >> 2;
    const int qd   = lane & 3;
    const float* xb = x + (size_t)b * NTOK * CDIM;
    const float* Kb = xb + LZ * CDIM;
    float* outb = out + (size_t)b * NTOK * CDIM;

    // ldmatrix per-lane geometry
    const int lrow  = lane & 15;             // A-tile row within 16
    const int lcolw = (lane >> 4) * 4;       // A col-half selector
    const int brow  = (lane & 7) + ((lane >> 4) << 3);  // B rows (two n-tiles)
    const int bcolw = ((lane >> 3) & 1) * 4;            // B col-half selector

    // ---------- Phase 1: S = Q K^T * scale (M=64, N=256, red=768) ----------
    const int warp_m = wid & 1;    // 0..1 -> 32 rows
    const int warp_n = wid >> 1;   // 0..7 -> 32 cols

    // word offsets (add s*8 per step)
    int aoff0 = (warp_m * 32 + 0  + lrow) * P1_LD + lcolw;
    int aoff1 = (warp_m * 32 + 16 + lrow) * P1_LD + lcolw;
    int boff0 = (warp_n * 32 + 0  + brow) * P1_LD + bcolw;
    int boff1 = (warp_n * 32 + 16 + brow) * P1_LD + bcolw;

    float acc[2][4][4];
#pragma unroll
    for (int i = 0; i < 2; ++i)
#pragma unroll
        for (int j = 0; j < 4; ++j)
#pragma unroll
            for (int r = 0; r < 4; ++r) acc[i][j][r] = 0.0f;

    auto load_tiles = [&](int it, uint32_t qb, uint32_t kb) {
        int c0 = it * 32;
        {   // Q: 64x32 = 512 16B chunks, 1/thread
            int row = tid >> 3, col = (tid & 7) * 4;
            cpa16(qb + (row * P1_LD + col) * 4, xb + row * CDIM + c0 + col);
        }
#pragma unroll
        for (int p = 0; p < 4; ++p) {  // K: 256x32 = 2048 chunks, 4/thread
            int id = p * 512 + tid;
            int row = id >> 3, col = (id & 7) * 4;
            cpa16(kb + (row * P1_LD + col) * 4, Kb + row * CDIM + c0 + col);
        }
        cpa_commit();
    };

    load_tiles(0, sqb0, skb0);
    for (int it = 0; it < 24; ++it) {
        int buf = it & 1;
        uint32_t qb = buf ? sqb1 : sqb0;
        uint32_t kb = buf ? skb1 : skb0;
        if (it + 1 < 24) {
            load_tiles(it + 1, buf ? sqb0 : sqb1, buf ? skb0 : skb1);
            cpa_wait<1>();
        } else {
            cpa_wait<0>();
        }
        __syncthreads();

#pragma unroll
        for (int s = 0; s < 4; ++s) {
            uint32_t a[2][4], bf[2][4];
            ldsm4(a[0], qb + (aoff0 + s * 8) * 4);
            ldsm4(a[1], qb + (aoff1 + s * 8) * 4);
            ldsm4(bf[0], kb + (boff0 + s * 8) * 4);
            ldsm4(bf[1], kb + (boff1 + s * 8) * 4);
#pragma unroll
            for (int p = 0; p < 2; ++p)
#pragma unroll
                for (int mt = 0; mt < 2; ++mt) {
                    mma8(acc[mt][2 * p],     a[mt][0], a[mt][1], a[mt][2], a[mt][3],
                         bf[p][0], bf[p][1]);
                    mma8(acc[mt][2 * p + 1], a[mt][0], a[mt][1], a[mt][2], a[mt][3],
                         bf[p][2], bf[p][3]);
                }
        }
        __syncthreads();
    }

    // store S (scaled) to smem
#pragma unroll
    for (int mt = 0; mt < 2; ++mt)
#pragma unroll
        for (int nt = 0; nt < 4; ++nt) {
            int r = warp_m * 32 + mt * 16 + grp;
            int c = warp_n * 32 + nt * 8 + 2 * qd;
            sS[r * SS_LD + c]           = acc[mt][nt][0] * SCALE;
            sS[r * SS_LD + c + 1]       = acc[mt][nt][1] * SCALE;
            sS[(r + 8) * SS_LD + c]     = acc[mt][nt][2] * SCALE;
            sS[(r + 8) * SS_LD + c + 1] = acc[mt][nt][3] * SCALE;
        }
    __syncthreads();

    // ---------- softmax (16 warps x 4 rows); store probs as tf32 (RNA) ----------
#pragma unroll
    for (int r = 0; r < 4; ++r) {
        int q = wid * 4 + r;
        float* row = sS + q * SS_LD;
        uint32_t* rowu = sSu + q * SS_LD;
        float v[8];
        float mx = -1e30f;
#pragma unroll
        for (int m = 0; m < 8; ++m) {
            v[m] = row[lane + 32 * m];
            mx = fmaxf(mx, v[m]);
        }
#pragma unroll
        for (int s = 16; s > 0; s >>= 1)
            mx = fmaxf(mx, __shfl_xor_sync(0xffffffffu, mx, s));
        float sum = 0.0f;
#pragma unroll
        for (int m = 0; m < 8; ++m) {
            v[m] = __expf(v[m] - mx);
            sum += v[m];
        }
#pragma unroll
        for (int s = 16; s > 0; s >>= 1)
            sum += __shfl_xor_sync(0xffffffffu, sum, s);
        float inv = 1.0f / sum;
#pragma unroll
        for (int m = 0; m < 8; ++m) rowu[lane + 32 * m] = f2t(v[m] * inv);
    }
    __syncthreads();

    // ---------- Phase 2: O = P @ K over 12 c-chunks of 64; fused K->out copy ----------
    const int warp_m2 = wid >> 2;        // 0..3 -> 16 rows
    const int warp_n2 = (wid & 3) * 16;  // 0..48

    const int a2off = (warp_m2 * 16 + lrow) * SS_LD + lcolw;  // + ks*8 per step

    for (int c0 = 0; c0 < CDIM; c0 += 64) {
        // fused loader: K chunk 256x64 -> smem AND out[:,64:,:] tail
#pragma unroll
        for (int p = 0; p < 8; ++p) {
            int id = p * 512 + tid;
            int row = id >> 4;
            int colv = (id & 15) * 4;
            float4 v = *(const float4*)(Kb + row * CDIM + c0 + colv);
            *(float4*)(sK2 + row * K2_LD + colv) = *(float4*)&v;
            *(float4*)(outb + (size_t)(LZ + row) * CDIM + c0 + colv) = v;
        }
        __syncthreads();

        float acc2[2][4];
#pragma unroll
        for (int i = 0; i < 2; ++i)
#pragma unroll
            for (int r = 0; r < 4; ++r) acc2[i][r] = 0.0f;

#pragma unroll 4
        for (int ks = 0; ks < 32; ++ks) {
            int kb = ks * 8;
            uint32_t a[4];
            ldsm4(a, ssb + (a2off + kb) * 4);
            int kq = kb + qd;
#pragma unroll
            for (int nt = 0; nt < 2; ++nt) {
                int nb = warp_n2 + nt * 8 + grp;
                uint32_t b0 = sK2[kq * K2_LD + nb];
                uint32_t b1 = sK2[(kq + 4) * K2_LD + nb];
                mma8(acc2[nt], a[0], a[1], a[2], a[3], b0, b1);
            }
        }
        __syncthreads();

        // stage transposed [c_local][t]
#pragma unroll
        for (int nt = 0; nt < 2; ++nt) {
            int cc = warp_n2 + nt * 8 + 2 * qd;
            int rq = warp_m2 * 16 + grp;
            stage[cc * STG_LD + rq]           = acc2[nt][0];
            stage[(cc + 1) * STG_LD + rq]     = acc2[nt][1];
            stage[cc * STG_LD + rq + 8]       = acc2[nt][2];
            stage[(cc + 1) * STG_LD + rq + 8] = acc2[nt][3];
        }
        __syncthreads();

        // coalesced write of 64x64 chunk of O^T
        float* dst = g_OT + (size_t)b * CDIM * LZ + (size_t)c0 * LZ;
#pragma unroll
        for (int p = 0; p < 2; ++p) {
            int idx = p * 2048 + tid * 4;
            int row = idx >> 6;
            int col = idx & 63;
            float4 v = *(float4*)&stage[row * STG_LD + col];
            *(float4*)&dst[row * LZ + col] = v;
        }
        __syncthreads();
    }
}

// ---------------- projection: Z = Y @ W^T + bias (tf32, cp.async dbuf, ldmatrix) ----------------
#define PJ_LD 36
extern __shared__ uint32_t psmem[];

__global__ __launch_bounds__(256, 2) void proj_k(const float* __restrict__ w,
                                                 const float* __restrict__ bias,
                                                 float* __restrict__ out) {
    uint32_t* sY[2] = { psmem, psmem + 2304 };
    uint32_t* sW[2] = { psmem + 4608, psmem + 4608 + 4608 };
    const uint32_t syb0 = (uint32_t)__cvta_generic_to_shared(sY[0]);
    const uint32_t syb1 = (uint32_t)__cvta_generic_to_shared(sY[1]);
    const uint32_t swb0 = (uint32_t)__cvta_generic_to_shared(sW[0]);
    const uint32_t swb1 = (uint32_t)__cvta_generic_to_shared(sW[1]);

    const int b  = blockIdx.y;
    const int o0 = blockIdx.x * 128;
    const float* Y = g_OT + (size_t)b * CDIM * LZ;
    const int tid  = threadIdx.x;
    const int wid  = tid >> 5;
    const int lane = tid & 31;
    const int grp  = lane >> 2;
    const int qd   = lane & 3;
    const int warp_m = wid >> 2;  // 0..1
    const int warp_n = wid & 3;   // 0..3

    const int lrow  = lane & 15;
    const int lcolw = (lane >> 4) * 4;
    const int brow  = (lane & 7) + ((lane >> 4) << 3);
    const int bcolw = ((lane >> 3) & 1) * 4;

    int aoff0 = (warp_m * 32 + 0  + lrow) * PJ_LD + lcolw;
    int aoff1 = (warp_m * 32 + 16 + lrow) * PJ_LD + lcolw;
    int boff0 = (warp_n * 32 + 0  + brow) * PJ_LD + bcolw;
    int boff1 = (warp_n * 32 + 16 + brow) * PJ_LD + bcolw;

    float acc[2][4][4];
#pragma unroll
    for (int i = 0; i < 2; ++i)
#pragma unroll
        for (int j = 0; j < 4; ++j)
#pragma unroll
            for (int r = 0; r < 4; ++r) acc[i][j][r] = 0.0f;

    auto load_tiles = [&](int it, uint32_t yb, uint32_t wb) {
        int k0 = it * 32;
#pragma unroll
        for (int p = 0; p < 2; ++p) {
            int id = p * 256 + tid;
            int row = id >> 3, col = (id & 7) * 4;
            cpa16(yb + (row * PJ_LD + col) * 4, Y + row * CDIM + k0 + col);
        }
#pragma unroll
        for (int p = 0; p < 4; ++p) {
            int id = p * 256 + tid;
            int row = id >> 3, col = (id & 7) * 4;
            cpa16(wb + (row * PJ_LD + col) * 4,
                  w + (size_t)(o0 + row) * CDIM + k0 + col);
        }
        cpa_commit();
    };

    load_tiles(0, syb0, swb0);
    for (int it = 0; it < 24; ++it) {
        int buf = it & 1;
        uint32_t yb = buf ? syb1 : syb0;
        uint32_t wb = buf ? swb1 : swb0;
        if (it + 1 < 24) {
            load_tiles(it + 1, buf ? syb0 : syb1, buf ? swb0 : swb1);
            cpa_wait<1>();
        } else {
            cpa_wait<0>();
        }
        __syncthreads();

#pragma unroll
        for (int s = 0; s < 4; ++s) {
            uint32_t a[2][4], bf[2][4];
            ldsm4(a[0], yb + (aoff0 + s * 8) * 4);
            ldsm4(a[1], yb + (aoff1 + s * 8) * 4);
            ldsm4(bf[0], wb + (boff0 + s * 8) * 4);
            ldsm4(bf[1], wb + (boff1 + s * 8) * 4);
#pragma unroll
            for (int p = 0; p < 2; ++p)
#pragma unroll
                for (int mt = 0; mt < 2; ++mt) {
                    mma8(acc[mt][2 * p],     a[mt][0], a[mt][1], a[mt][2], a[mt][3],
                         bf[p][0], bf[p][1]);
                    mma8(acc[mt][2 * p + 1], a[mt][0], a[mt][1], a[mt][2], a[mt][3],
                         bf[p][2], bf[p][3]);
                }
        }
        __syncthreads();
    }

    // epilogue: bias + store
#pragma unroll
    for (int mt = 0; mt < 2; ++mt)
#pragma unroll
        for (int nt = 0; nt < 4; ++nt) {
            int q = warp_m * 32 + mt * 16 + grp;
            int o = o0 + warp_n * 32 + nt * 8 + 2 * qd;
            float bv0 = bias[o], bv1 = bias[o + 1];
            float2 v0 = make_float2(acc[mt][nt][0] + bv0, acc[mt][nt][1] + bv1);
            float2 v1 = make_float2(acc[mt][nt][2] + bv0, acc[mt][nt][3] + bv1);
            *(float2*)&out[(size_t)b * NTOK * CDIM + (size_t)q * CDIM + o] = v0;
            *(float2*)&out[(size_t)b * NTOK * CDIM + (size_t)(q + 8) * CDIM + o] = v1;
        }
}

extern "C" void kernel_launch(void* const* d_in, const int* in_sizes, int n_in,
                              void* d_out, int out_size) {
    const float* x    = (const float*)d_in[0];
    const float* w    = (const float*)d_in[1];
    const float* bias = (const float*)d_in[2];
    float* out = (float*)d_out;

    size_t smemA = (size_t)SMEM_WORDS * sizeof(float);  // 158720 B
    cudaFuncSetAttribute(attn_k, cudaFuncAttributeMaxDynamicSharedMemorySize, (int)smemA);
    attn_k<<<BATCH, 512, smemA>>>(x, out);

    size_t smemP = 13824 * sizeof(uint32_t);  // 55296 B
    cudaFuncSetAttribute(proj_k, cudaFuncAttributeMaxDynamicSharedMemorySize, (int)smemP);
    proj_k<<<dim3(6, BATCH), 256, smemP>>>(w, bias, out);
}

// round 5
// speedup vs baseline: 1.2123x; 1.2123x over previous
#include <cuda_runtime.h>
#include <cstdint>

#define BATCH 256
#define NTOK  320
#define CDIM  768
#define LZ    64
#define LK    256
#define SCALE 0.125f

// Scratch: O transposed per batch; flat == Y_all (16384 x 768) row-major.
__device__ float g_OT[(size_t)BATCH * CDIM * LZ];

__device__ __forceinline__ uint32_t f2t(float x) {
    uint32_t r;
    asm("cvt.rna.tf32.f32 %0, %1;" : "=r"(r) : "f"(x));
    return r;
}

__device__ __forceinline__ void mma8(float* d, const uint32_t* a,
                                     uint32_t b0, uint32_t b1) {
    asm volatile(
        "mma.sync.aligned.m16n8k8.row.col.f32.tf32.tf32.f32 "
        "{%0,%1,%2,%3}, {%4,%5,%6,%7}, {%8,%9}, {%0,%1,%2,%3};\n"
        : "+f"(d[0]), "+f"(d[1]), "+f"(d[2]), "+f"(d[3])
        : "r"(a[0]), "r"(a[1]), "r"(a[2]), "r"(a[3]), "r"(b0), "r"(b1));
}

__device__ __forceinline__ void ldsm4(uint32_t* r, uint32_t saddr) {
    asm volatile("ldmatrix.sync.aligned.m8n8.x4.shared.b16 {%0,%1,%2,%3}, [%4];"
                 : "=r"(r[0]), "=r"(r[1]), "=r"(r[2]), "=r"(r[3]) : "r"(saddr));
}

__device__ __forceinline__ void cpa16(uint32_t saddr, const void* gaddr) {
    asm volatile("cp.async.cg.shared.global [%0], [%1], 16;\n"
                 :: "r"(saddr), "l"(gaddr));
}
__device__ __forceinline__ void cpa_commit() {
    asm volatile("cp.async.commit_group;\n");
}
template <int N>
__device__ __forceinline__ void cpa_wait() {
    asm volatile("cp.async.wait_group %0;\n" :: "n"(N));
}

// ---------------- fused attention per batch (512 threads) ----------------
#define P1_LD  36   // %8==4 word-chunks -> ldsm rows conflict-free
#define SS_LD  260
#define K2_LD  72   // %32==8 -> scalar B loads conflict-free (bank=8*qd+grp)
#define STG_LD 68

#define OFF_POOL (LZ * SS_LD)                 // 16640 words
// pool: phase1 3 stages x (Q 64x36 + K 256x36 = 11520) = 34560
//       phase2 K2 256x72 = 18432 + stage 4x(64x68) = 17408 -> 35840
#define POOL_WORDS 35840
#define SMEM_WORDS (OFF_POOL + POOL_WORDS)    // 52480 words = 209920 B

#define STAGE_W 11520

extern __shared__ float smem[];

__global__ __launch_bounds__(512, 1) void attn_k(const float* __restrict__ x,
                                                 float* __restrict__ out) {
    float*    sS  = smem;                      // 64 x 260 scores -> tf32 probs
    uint32_t* sSu = (uint32_t*)smem;
    uint32_t* pool = (uint32_t*)(smem + OFF_POOL);
    uint32_t* sK2   = pool;                    // phase 2: 256 x 72
    float*    stage = (float*)(pool + 18432);  // phase 2: 4 x (64 x 68)

    const uint32_t ssb   = (uint32_t)__cvta_generic_to_shared(sS);
    const uint32_t poolb = (uint32_t)__cvta_generic_to_shared(pool);
    const uint32_t k2b   = poolb;

    const int b    = blockIdx.x;
    const int tid  = threadIdx.x;
    const int wid  = tid >> 5;
    const int lane = tid & 31;
    const int grp  = lane >> 2;
    const int qd   = lane & 3;
    const float* xb = x + (size_t)b * NTOK * CDIM;
    const float* Kb = xb + LZ * CDIM;
    float* outb = out + (size_t)b * NTOK * CDIM;

    const int lrow  = lane & 15;
    const int lcolw = (lane >> 4) * 4;
    const int brow  = (lane & 7) + ((lane >> 4) << 3);
    const int bcolw = ((lane >> 3) & 1) * 4;

    // ---------- Phase 1: S = Q K^T * scale (M=64, N=256, red=768) ----------
    const int warp_m = wid & 1;    // 32 rows
    const int warp_n = wid >> 1;   // 32 cols

    const int aoff0 = (warp_m * 32 + 0  + lrow) * P1_LD + lcolw;
    const int aoff1 = (warp_m * 32 + 16 + lrow) * P1_LD + lcolw;
    const int boff0 = (warp_n * 32 + 0  + brow) * P1_LD + bcolw;
    const int boff1 = (warp_n * 32 + 16 + brow) * P1_LD + bcolw;

    float acc[2][4][4];
#pragma unroll
    for (int i = 0; i < 2; ++i)
#pragma unroll
        for (int j = 0; j < 4; ++j)
#pragma unroll
            for (int r = 0; r < 4; ++r) acc[i][j][r] = 0.0f;

    auto load_tiles = [&](int it, int st) {
        int c0 = it * 32;
        uint32_t qb = poolb + (st * STAGE_W) * 4;
        uint32_t kb = qb + 2304 * 4;
        {   // Q: 64x32 = 512 chunks, 1/thread
            int row = tid >> 3, col = (tid & 7) * 4;
            cpa16(qb + (row * P1_LD + col) * 4, xb + row * CDIM + c0 + col);
        }
#pragma unroll
        for (int p = 0; p < 4; ++p) {  // K: 256x32 = 2048 chunks, 4/thread
            int id = p * 512 + tid;
            int row = id >> 3, col = (id & 7) * 4;
            cpa16(kb + (row * P1_LD + col) * 4, Kb + row * CDIM + c0 + col);
        }
        cpa_commit();
    };

    load_tiles(0, 0);
    load_tiles(1, 1);
    for (int it = 0; it < 24; ++it) {
        if (it == 23) cpa_wait<0>(); else cpa_wait<1>();
        __syncthreads();
        if (it + 2 < 24) load_tiles(it + 2, (it + 2) % 3);

        uint32_t qb = poolb + ((it % 3) * STAGE_W) * 4;
        uint32_t kb = qb + 2304 * 4;
#pragma unroll
        for (int s = 0; s < 4; ++s) {
            uint32_t a[2][4], bf[2][4];
            ldsm4(a[0], qb + (aoff0 + s * 8) * 4);
            ldsm4(a[1], qb + (aoff1 + s * 8) * 4);
            ldsm4(bf[0], kb + (boff0 + s * 8) * 4);
            ldsm4(bf[1], kb + (boff1 + s * 8) * 4);
#pragma unroll
            for (int p = 0; p < 2; ++p)
#pragma unroll
                for (int mt = 0; mt < 2; ++mt) {
                    mma8(acc[mt][2 * p],     a[mt], bf[p][0], bf[p][1]);
                    mma8(acc[mt][2 * p + 1], a[mt], bf[p][2], bf[p][3]);
                }
        }
    }
    __syncthreads();  // phase-1 reads done before sS writes

    // store S (scaled)
#pragma unroll
    for (int mt = 0; mt < 2; ++mt)
#pragma unroll
        for (int nt = 0; nt < 4; ++nt) {
            int r = warp_m * 32 + mt * 16 + grp;
            int c = warp_n * 32 + nt * 8 + 2 * qd;
            sS[r * SS_LD + c]           = acc[mt][nt][0] * SCALE;
            sS[r * SS_LD + c + 1]       = acc[mt][nt][1] * SCALE;
            sS[(r + 8) * SS_LD + c]     = acc[mt][nt][2] * SCALE;
            sS[(r + 8) * SS_LD + c + 1] = acc[mt][nt][3] * SCALE;
        }
    __syncthreads();

    // ---------- softmax (16 warps x 4 rows) -> tf32 probs ----------
#pragma unroll
    for (int r = 0; r < 4; ++r) {
        int q = wid * 4 + r;
        float* row = sS + q * SS_LD;
        uint32_t* rowu = sSu + q * SS_LD;
        float v[8];
        float mx = -1e30f;
#pragma unroll
        for (int m = 0; m < 8; ++m) {
            v[m] = row[lane + 32 * m];
            mx = fmaxf(mx, v[m]);
        }
#pragma unroll
        for (int s = 16; s > 0; s >>= 1)
            mx = fmaxf(mx, __shfl_xor_sync(0xffffffffu, mx, s));
        float sum = 0.0f;
#pragma unroll
        for (int m = 0; m < 8; ++m) {
            v[m] = __expf(v[m] - mx);
            sum += v[m];
        }
#pragma unroll
        for (int s = 16; s > 0; s >>= 1)
            sum += __shfl_xor_sync(0xffffffffu, sum, s);
        float inv = 1.0f / sum;
#pragma unroll
        for (int m = 0; m < 8; ++m) rowu[lane + 32 * m] = f2t(v[m] * inv);
    }
    __syncthreads();

    // ---------- Phase 2: O = P @ K; P fragments register-resident ----------
    const int kg      = wid & 3;          // k-split: tokens [kg*64, kg*64+64)
    const int warp_n2 = (wid >> 2) & 1;   // 32 cols of 64-chunk
    const int warp_m2 = wid >> 3;         // 32 rows

    // issue first K2 chunk load (256 x 64 -> [k][c], 8 chunks/thread)
    auto load_k2 = [&](int c0) {
#pragma unroll
        for (int p = 0; p < 8; ++p) {
            int id = p * 512 + tid;
            int row = id >> 4, colv = (id & 15) * 4;
            cpa16(k2b + (row * K2_LD + colv) * 4, Kb + row * CDIM + c0 + colv);
        }
        cpa_commit();
    };
    load_k2(0);

    // load P fragments once: 2 mtiles x 8 ksteps
    uint32_t aP[2][8][4];
#pragma unroll
    for (int mt = 0; mt < 2; ++mt)
#pragma unroll
        for (int ks = 0; ks < 8; ++ks)
            ldsm4(aP[mt][ks],
                  ssb + ((warp_m2 * 32 + mt * 16 + lrow) * SS_LD +
                         kg * 64 + ks * 8 + lcolw) * 4);

    float* stg = stage + kg * (64 * STG_LD);

    for (int cc0 = 0; cc0 < 12; ++cc0) {
        int c0 = cc0 * 64;
        cpa_wait<0>();
        __syncthreads();  // K2 ready; previous reduce done

        float acc2[2][4][4];
#pragma unroll
        for (int i = 0; i < 2; ++i)
#pragma unroll
            for (int j = 0; j < 4; ++j)
#pragma unroll
                for (int r = 0; r < 4; ++r) acc2[i][j][r] = 0.0f;

#pragma unroll
        for (int ks = 0; ks < 8; ++ks) {
            int kq = kg * 64 + ks * 8 + qd;
#pragma unroll
            for (int nt = 0; nt < 4; ++nt) {
                int nb = warp_n2 * 32 + nt * 8 + grp;
                uint32_t b0 = sK2[kq * K2_LD + nb];
                uint32_t b1 = sK2[(kq + 4) * K2_LD + nb];
                mma8(acc2[0][nt], aP[0][ks], b0, b1);
                mma8(acc2[1][nt], aP[1][ks], b0, b1);
            }
        }
        __syncthreads();  // all K2 reads done

        if (cc0 + 1 < 12) load_k2(c0 + 64);

        // fused out-tail copy for this chunk (K data hot in L2)
#pragma unroll
        for (int p = 0; p < 8; ++p) {
            int id = p * 512 + tid;
            int row = id >> 4, colv = (id & 15) * 4;
            float4 v = *(const float4*)(Kb + row * CDIM + c0 + colv);
            *(float4*)(outb + (size_t)(LZ + row) * CDIM + c0 + colv) = v;
        }

        // stage partials [c_local][t] per kg copy
#pragma unroll
        for (int mt = 0; mt < 2; ++mt)
#pragma unroll
            for (int nt = 0; nt < 4; ++nt) {
                int cc = warp_n2 * 32 + nt * 8 + 2 * qd;
                int rq = warp_m2 * 32 + mt * 16 + grp;
                stg[cc * STG_LD + rq]           = acc2[mt][nt][0];
                stg[(cc + 1) * STG_LD + rq]     = acc2[mt][nt][1];
                stg[cc * STG_LD + rq + 8]       = acc2[mt][nt][2];
                stg[(cc + 1) * STG_LD + rq + 8] = acc2[mt][nt][3];
            }
        __syncthreads();  // stage complete

        // reduce 4 k-partials and write 64x64 chunk of O^T (coalesced)
        float* dst = g_OT + (size_t)b * CDIM * LZ + (size_t)c0 * LZ;
#pragma unroll
        for (int p = 0; p < 2; ++p) {
            int fid = p * 512 + tid;
            int row = fid >> 4, c4 = (fid & 15) * 4;
            float4 s0 = *(float4*)&stage[0 * 4352 + row * STG_LD + c4];
            float4 s1 = *(float4*)&stage[1 * 4352 + row * STG_LD + c4];
            float4 s2 = *(float4*)&stage[2 * 4352 + row * STG_LD + c4];
            float4 s3 = *(float4*)&stage[3 * 4352 + row * STG_LD + c4];
            float4 o;
            o.x = (s0.x + s1.x) + (s2.x + s3.x);
            o.y = (s0.y + s1.y) + (s2.y + s3.y);
            o.z = (s0.z + s1.z) + (s2.z + s3.z);
            o.w = (s0.w + s1.w) + (s2.w + s3.w);
            *(float4*)&dst[row * LZ + c4] = o;
        }
    }
}

// ---------------- projection: flat GEMM Y_all(16384x768) @ W^T + bias ----------------
#define PJ_LD 36
#define PJ_STAGE_W (2 * 128 * PJ_LD)   // A + B per stage = 9216 words
extern __shared__ uint32_t psmem[];

__global__ __launch_bounds__(256, 2) void proj_k(const float* __restrict__ w,
                                                 const float* __restrict__ bias,
                                                 float* __restrict__ out) {
    const int o0 = blockIdx.x * 128;
    const int m0 = blockIdx.y * 128;
    const float* Y = g_OT;  // flat (16384, 768)
    const int tid  = threadIdx.x;
    const int wid  = tid >> 5;
    const int lane = tid & 31;
    const int grp  = lane >> 2;
    const int qd   = lane & 3;
    const int warp_m = wid >> 2;  // 0..1 -> 64 rows
    const int warp_n = wid & 3;   // 0..3 -> 32 cols

    const uint32_t pb = (uint32_t)__cvta_generic_to_shared(psmem);

    const int lrow  = lane & 15;
    const int lcolw = (lane >> 4) * 4;
    const int brow  = (lane & 7) + ((lane >> 4) << 3);
    const int bcolw = ((lane >> 3) & 1) * 4;

    int aoff[4], boff0, boff1;
#pragma unroll
    for (int mt = 0; mt < 4; ++mt)
        aoff[mt] = (warp_m * 64 + mt * 16 + lrow) * PJ_LD + lcolw;
    boff0 = (128 * PJ_LD) + (warp_n * 32 + 0  + brow) * PJ_LD + bcolw;
    boff1 = (128 * PJ_LD) + (warp_n * 32 + 16 + brow) * PJ_LD + bcolw;

    float acc[4][4][4];
#pragma unroll
    for (int i = 0; i < 4; ++i)
#pragma unroll
        for (int j = 0; j < 4; ++j)
#pragma unroll
            for (int r = 0; r < 4; ++r) acc[i][j][r] = 0.0f;

    auto load_tiles = [&](int it, int st) {
        int k0 = it * 32;
        uint32_t ab = pb + (st * PJ_STAGE_W) * 4;
        uint32_t bb = ab + (128 * PJ_LD) * 4;
#pragma unroll
        for (int p = 0; p < 4; ++p) {  // A: 128x32 = 1024 chunks
            int id = p * 256 + tid;
            int row = id >> 3, col = (id & 7) * 4;
            cpa16(ab + (row * PJ_LD + col) * 4,
                  Y + (size_t)(m0 + row) * CDIM + k0 + col);
        }
#pragma unroll
        for (int p = 0; p < 4; ++p) {  // B: 128x32
            int id = p * 256 + tid;
            int row = id >> 3, col = (id & 7) * 4;
            cpa16(bb + (row * PJ_LD + col) * 4,
                  w + (size_t)(o0 + row) * CDIM + k0 + col);
        }
        cpa_commit();
    };

    load_tiles(0, 0);
    load_tiles(1, 1);
    for (int it = 0; it < 24; ++it) {
        if (it == 23) cpa_wait<0>(); else cpa_wait<1>();
        __syncthreads();
        if (it + 2 < 24) load_tiles(it + 2, (it + 2) % 3);

        uint32_t ab = pb + ((it % 3) * PJ_STAGE_W) * 4;
#pragma unroll
        for (int s = 0; s < 4; ++s) {
            uint32_t a[4][4], bf[2][4];
            ldsm4(bf[0], ab + (boff0 + s * 8) * 4);
            ldsm4(bf[1], ab + (boff1 + s * 8) * 4);
#pragma unroll
            for (int mt = 0; mt < 4; ++mt)
                ldsm4(a[mt], ab + (aoff[mt] + s * 8) * 4);
#pragma unroll
            for (int mt = 0; mt < 4; ++mt)
#pragma unroll
                for (int p = 0; p < 2; ++p) {
                    mma8(acc[mt][2 * p],     a[mt], bf[p][0], bf[p][1]);
                    mma8(acc[mt][2 * p + 1], a[mt], bf[p][2], bf[p][3]);
                }
        }
    }

    // epilogue: bias + store (row -> (b, q))
#pragma unroll
    for (int mt = 0; mt < 4; ++mt)
#pragma unroll
        for (int nt = 0; nt < 4; ++nt) {
            int gr = m0 + warp_m * 64 + mt * 16 + grp;
            int o  = o0 + warp_n * 32 + nt * 8 + 2 * qd;
            float bv0 = bias[o], bv1 = bias[o + 1];
            int b0i = gr >> 6, q0 = gr & 63;
            int b1i = (gr + 8) >> 6, q1 = (gr + 8) & 63;
            float2 v0 = make_float2(acc[mt][nt][0] + bv0, acc[mt][nt][1] + bv1);
            float2 v1 = make_float2(acc[mt][nt][2] + bv0, acc[mt][nt][3] + bv1);
            *(float2*)&out[(size_t)b0i * NTOK * CDIM + (size_t)q0 * CDIM + o] = v0;
            *(float2*)&out[(size_t)b1i * NTOK * CDIM + (size_t)q1 * CDIM + o] = v1;
        }
}

extern "C" void kernel_launch(void* const* d_in, const int* in_sizes, int n_in,
                              void* d_out, int out_size) {
    const float* x    = (const float*)d_in[0];
    const float* w    = (const float*)d_in[1];
    const float* bias = (const float*)d_in[2];
    float* out = (float*)d_out;

    size_t smemA = (size_t)SMEM_WORDS * sizeof(float);  // 209920 B
    cudaFuncSetAttribute(attn_k, cudaFuncAttributeMaxDynamicSharedMemorySize, (int)smemA);
    attn_k<<<BATCH, 512, smemA>>>(x, out);

    size_t smemP = (size_t)(3 * PJ_STAGE_W) * sizeof(uint32_t);  // 110592 B
    cudaFuncSetAttribute(proj_k, cudaFuncAttributeMaxDynamicSharedMemorySize, (int)smemP);
    proj_k<<<dim3(6, 128), 256, smemP>>>(w, bias, out);
}

// round 6
// speedup vs baseline: 1.3218x; 1.0903x over previous
#include <cuda_runtime.h>
#include <cstdint>

#define BATCH 256
#define NTOK  320
#define CDIM  768
#define LZ    64
#define LK    256
#define SCALE 0.125f

// Scratch: O transposed per batch; flat == Y_all (16384 x 768) row-major.
__device__ float g_OT[(size_t)BATCH * CDIM * LZ];

__device__ __forceinline__ uint32_t f2t(float x) {
    uint32_t r;
    asm("cvt.rna.tf32.f32 %0, %1;" : "=r"(r) : "f"(x));
    return r;
}

__device__ __forceinline__ void mma8(float* d, const uint32_t* a,
                                     uint32_t b0, uint32_t b1) {
    asm volatile(
        "mma.sync.aligned.m16n8k8.row.col.f32.tf32.tf32.f32 "
        "{%0,%1,%2,%3}, {%4,%5,%6,%7}, {%8,%9}, {%0,%1,%2,%3};\n"
        : "+f"(d[0]), "+f"(d[1]), "+f"(d[2]), "+f"(d[3])
        : "r"(a[0]), "r"(a[1]), "r"(a[2]), "r"(a[3]), "r"(b0), "r"(b1));
}

__device__ __forceinline__ void ldsm4(uint32_t* r, uint32_t saddr) {
    asm volatile("ldmatrix.sync.aligned.m8n8.x4.shared.b16 {%0,%1,%2,%3}, [%4];"
                 : "=r"(r[0]), "=r"(r[1]), "=r"(r[2]), "=r"(r[3]) : "r"(saddr));
}

__device__ __forceinline__ void cpa16(uint32_t saddr, const void* gaddr) {
    asm volatile("cp.async.cg.shared.global [%0], [%1], 16;\n"
                 :: "r"(saddr), "l"(gaddr));
}
__device__ __forceinline__ void cpa_commit() {
    asm volatile("cp.async.commit_group;\n");
}
template <int N>
__device__ __forceinline__ void cpa_wait() {
    asm volatile("cp.async.wait_group %0;\n" :: "n"(N));
}

// ---------------- fused attention per batch (256 threads, occ 2, single wave) ----------------
#define P1_LD  36    // ldsm rows on distinct 16B groups (36/4=9, 9r mod 8 = r)
#define SS_LD  260
#define K2_LD  40    // %32==8 -> scalar B loads conflict-free (bank=8*qd+grp)
#define STG_LD 68

#define STAGE_W 11520                      // phase1: Q 64x36 + K 256x36 per stage
// region words: max(phase1 2*11520=23040, phase2 2*10240 + 2*2176 = 24832)
#define SMEM_WORDS 24832                   // 99328 B -> occ 2
#define K2_BUF_W 10240                     // 256 x 40
#define STG_OFF  20480

extern __shared__ float smem[];

__global__ __launch_bounds__(256, 2) void attn_k(const float* __restrict__ x,
                                                 float* __restrict__ out) {
    float*    sS  = smem;                     // 64 x 260 (words [0,16640), time-muxed)
    uint32_t* sSu = (uint32_t*)smem;
    uint32_t* pool = (uint32_t*)smem;
    float*    stage = smem + STG_OFF;         // phase 2: 2 x (32 x 68)

    const uint32_t ssb   = (uint32_t)__cvta_generic_to_shared(sS);
    const uint32_t poolb = ssb;

    const int b    = blockIdx.x;
    const int tid  = threadIdx.x;
    const int wid  = tid >> 5;
    const int lane = tid & 31;
    const int grp  = lane >> 2;
    const int qd   = lane & 3;
    const float* xb = x + (size_t)b * NTOK * CDIM;
    const float* Kb = xb + LZ * CDIM;
    float* outb = out + (size_t)b * NTOK * CDIM;

    const int lrow  = lane & 15;
    const int lcolw = (lane >> 4) * 4;
    const int brow  = (lane & 7) + ((lane >> 4) << 3);
    const int bcolw = ((lane >> 3) & 1) * 4;

    // ---------- Phase 1: S = Q K^T * scale (M=64, N=256, red=768) ----------
    const int warp_m = wid >> 2;   // 0..1 -> 32 rows
    const int warp_n = wid & 3;    // 0..3 -> 64 cols

    const int aoff0 = (warp_m * 32 + 0  + lrow) * P1_LD + lcolw;
    const int aoff1 = (warp_m * 32 + 16 + lrow) * P1_LD + lcolw;
    int boff[4];
#pragma unroll
    for (int nt2 = 0; nt2 < 4; ++nt2)
        boff[nt2] = (warp_n * 64 + nt2 * 16 + brow) * P1_LD + bcolw;

    float acc[2][8][4];
#pragma unroll
    for (int i = 0; i < 2; ++i)
#pragma unroll
        for (int j = 0; j < 8; ++j)
#pragma unroll
            for (int r = 0; r < 4; ++r) acc[i][j][r] = 0.0f;

    auto load_tiles = [&](int it, int st) {
        int c0 = it * 32;
        uint32_t qb = poolb + (st * STAGE_W) * 4;
        uint32_t kb = qb + 2304 * 4;
#pragma unroll
        for (int p = 0; p < 2; ++p) {  // Q 64x32: 512 chunks, 2/thread
            int id = p * 256 + tid;
            int row = id >> 3, col = (id & 7) * 4;
            cpa16(qb + (row * P1_LD + col) * 4, xb + row * CDIM + c0 + col);
        }
#pragma unroll
        for (int p = 0; p < 8; ++p) {  // K 256x32: 2048 chunks, 8/thread
            int id = p * 256 + tid;
            int row = id >> 3, col = (id & 7) * 4;
            cpa16(kb + (row * P1_LD + col) * 4, Kb + row * CDIM + c0 + col);
        }
        cpa_commit();
    };

    load_tiles(0, 0);
    for (int it = 0; it < 24; ++it) {
        cpa_wait<0>();
        __syncthreads();  // buf(it&1) ready; all warps done with other buf
        if (it + 1 < 24) load_tiles(it + 1, (it + 1) & 1);

        uint32_t qb = poolb + ((it & 1) * STAGE_W) * 4;
        uint32_t kb = qb + 2304 * 4;
#pragma unroll
        for (int s = 0; s < 4; ++s) {
            uint32_t a[2][4], bf[4][4];
            ldsm4(a[0], qb + (aoff0 + s * 8) * 4);
            ldsm4(a[1], qb + (aoff1 + s * 8) * 4);
#pragma unroll
            for (int nt2 = 0; nt2 < 4; ++nt2)
                ldsm4(bf[nt2], kb + (boff[nt2] + s * 8) * 4);
#pragma unroll
            for (int nt2 = 0; nt2 < 4; ++nt2)
#pragma unroll
                for (int mt = 0; mt < 2; ++mt) {
                    mma8(acc[mt][2 * nt2],     a[mt], bf[nt2][0], bf[nt2][1]);
                    mma8(acc[mt][2 * nt2 + 1], a[mt], bf[nt2][2], bf[nt2][3]);
                }
        }
    }
    __syncthreads();  // all phase-1 reads finished; region becomes S

    // store S (scaled) into S region
#pragma unroll
    for (int mt = 0; mt < 2; ++mt)
#pragma unroll
        for (int nt = 0; nt < 8; ++nt) {
            int r = warp_m * 32 + mt * 16 + grp;
            int c = warp_n * 64 + nt * 8 + 2 * qd;
            sS[r * SS_LD + c]           = acc[mt][nt][0] * SCALE;
            sS[r * SS_LD + c + 1]       = acc[mt][nt][1] * SCALE;
            sS[(r + 8) * SS_LD + c]     = acc[mt][nt][2] * SCALE;
            sS[(r + 8) * SS_LD + c + 1] = acc[mt][nt][3] * SCALE;
        }
    __syncthreads();

    // ---------- softmax (8 warps x 8 rows) -> tf32 probs in place ----------
#pragma unroll
    for (int r = 0; r < 8; ++r) {
        int q = wid * 8 + r;
        float* row = sS + q * SS_LD;
        uint32_t* rowu = sSu + q * SS_LD;
        float v[8];
        float mx = -1e30f;
#pragma unroll
        for (int m = 0; m < 8; ++m) {
            v[m] = row[lane + 32 * m];
            mx = fmaxf(mx, v[m]);
        }
#pragma unroll
        for (int s = 16; s > 0; s >>= 1)
            mx = fmaxf(mx, __shfl_xor_sync(0xffffffffu, mx, s));
        float sum = 0.0f;
#pragma unroll
        for (int m = 0; m < 8; ++m) {
            v[m] = __expf(v[m] - mx);
            sum += v[m];
        }
#pragma unroll
        for (int s = 16; s > 0; s >>= 1)
            sum += __shfl_xor_sync(0xffffffffu, sum, s);
        float inv = 1.0f / sum;
#pragma unroll
        for (int m = 0; m < 8; ++m) rowu[lane + 32 * m] = f2t(v[m] * inv);
    }
    __syncthreads();

    // ---------- load P fragments once (register-resident), then free S ----------
    const int warp_m2 = wid & 3;   // 16 rows
    const int kg      = wid >> 2;  // k half: tokens [kg*128, kg*128+128)

    uint32_t aP[16][4];
#pragma unroll
    for (int ks = 0; ks < 16; ++ks)
        ldsm4(aP[ks], ssb + ((warp_m2 * 16 + lrow) * SS_LD +
                             kg * 128 + ks * 8 + lcolw) * 4);
    __syncthreads();  // S fully consumed; region becomes K2 buffers

    // ---------- Phase 2: O^T in 24 c-chunks of 32 ----------
    uint32_t* sK2[2] = { pool, pool + K2_BUF_W };
    const uint32_t k2b0 = poolb;
    const uint32_t k2b1 = poolb + K2_BUF_W * 4;

    auto load_k2 = [&](int it, int st) {
        int c0 = it * 32;
        uint32_t kb = st ? k2b1 : k2b0;
#pragma unroll
        for (int p = 0; p < 8; ++p) {
            int id = p * 256 + tid;
            int row = id >> 3, col = (id & 7) * 4;
            cpa16(kb + (row * K2_LD + col) * 4, Kb + row * CDIM + c0 + col);
        }
        cpa_commit();
    };

    float* stg = stage + kg * (32 * STG_LD);

    load_k2(0, 0);
    for (int it = 0; it < 24; ++it) {
        int c0 = it * 32;
        cpa_wait<0>();
        __syncthreads();  // K2 buf ready; previous reduce done
        if (it + 1 < 24) load_k2(it + 1, (it + 1) & 1);

        uint32_t* K2 = sK2[it & 1];

        float acc2[4][4];
#pragma unroll
        for (int i = 0; i < 4; ++i)
#pragma unroll
            for (int r = 0; r < 4; ++r) acc2[i][r] = 0.0f;

#pragma unroll
        for (int ks = 0; ks < 16; ++ks) {
            int kq = kg * 128 + ks * 8 + qd;
#pragma unroll
            for (int nt = 0; nt < 4; ++nt) {
                int nb = nt * 8 + grp;
                uint32_t b0 = K2[kq * K2_LD + nb];
                uint32_t b1 = K2[(kq + 4) * K2_LD + nb];
                mma8(acc2[nt], aP[ks], b0, b1);
            }
        }

        // fused tail copy out[:,64:,:] chunk (source hot in L2)
#pragma unroll
        for (int p = 0; p < 8; ++p) {
            int id = p * 256 + tid;
            int row = id >> 3, col = (id & 7) * 4;
            float4 v = *(const float4*)(Kb + row * CDIM + c0 + col);
            *(float4*)(outb + (size_t)(LZ + row) * CDIM + c0 + col) = v;
        }

        // stage partials transposed [c_local][t], one copy per kg
#pragma unroll
        for (int nt = 0; nt < 4; ++nt) {
            int cc = nt * 8 + 2 * qd;
            int rq = warp_m2 * 16 + grp;
            stg[cc * STG_LD + rq]           = acc2[nt][0];
            stg[(cc + 1) * STG_LD + rq]     = acc2[nt][1];
            stg[cc * STG_LD + rq + 8]       = acc2[nt][2];
            stg[(cc + 1) * STG_LD + rq + 8] = acc2[nt][3];
        }
        __syncthreads();

        // reduce 2 k-halves, write 32x64 O^T chunk (coalesced)
        float* dst = g_OT + (size_t)b * CDIM * LZ + (size_t)c0 * LZ;
#pragma unroll
        for (int p = 0; p < 2; ++p) {
            int fid = p * 256 + tid;
            int row = fid >> 4, c4 = (fid & 15) * 4;
            float4 s0 = *(float4*)&stage[row * STG_LD + c4];
            float4 s1 = *(float4*)&stage[32 * STG_LD + row * STG_LD + c4];
            float4 o;
            o.x = s0.x + s1.x; o.y = s0.y + s1.y;
            o.z = s0.z + s1.z; o.w = s0.w + s1.w;
            *(float4*)&dst[row * LZ + c4] = o;
        }
    }
}

// ---------------- projection: flat GEMM Y_all(16384x768) @ W^T + bias ----------------
#define PJ_LD 36
#define PJ_STAGE_W (2 * 128 * PJ_LD)   // 9216 words
extern __shared__ uint32_t psmem[];

__global__ __launch_bounds__(256, 2) void proj_k(const float* __restrict__ w,
                                                 const float* __restrict__ bias,
                                                 float* __restrict__ out) {
    const int o0 = blockIdx.x * 128;
    const int m0 = blockIdx.y * 128;
    const float* Y = g_OT;
    const int tid  = threadIdx.x;
    const int wid  = tid >> 5;
    const int lane = tid & 31;
    const int grp  = lane >> 2;
    const int qd   = lane & 3;
    const int warp_m = wid >> 2;  // 0..1 -> 64 rows
    const int warp_n = wid & 3;   // 0..3 -> 32 cols

    const uint32_t pb = (uint32_t)__cvta_generic_to_shared(psmem);

    const int lrow  = lane & 15;
    const int lcolw = (lane >> 4) * 4;
    const int brow  = (lane & 7) + ((lane >> 4) << 3);
    const int bcolw = ((lane >> 3) & 1) * 4;

    int aoff[4], boff0, boff1;
#pragma unroll
    for (int mt = 0; mt < 4; ++mt)
        aoff[mt] = (warp_m * 64 + mt * 16 + lrow) * PJ_LD + lcolw;
    boff0 = (128 * PJ_LD) + (warp_n * 32 + 0  + brow) * PJ_LD + bcolw;
    boff1 = (128 * PJ_LD) + (warp_n * 32 + 16 + brow) * PJ_LD + bcolw;

    float acc[4][4][4];
#pragma unroll
    for (int i = 0; i < 4; ++i)
#pragma unroll
        for (int j = 0; j < 4; ++j)
#pragma unroll
            for (int r = 0; r < 4; ++r) acc[i][j][r] = 0.0f;

    auto load_tiles = [&](int it, int st) {
        int k0 = it * 32;
        uint32_t ab = pb + (st * PJ_STAGE_W) * 4;
        uint32_t bb = ab + (128 * PJ_LD) * 4;
#pragma unroll
        for (int p = 0; p < 4; ++p) {
            int id = p * 256 + tid;
            int row = id >> 3, col = (id & 7) * 4;
            cpa16(ab + (row * PJ_LD + col) * 4,
                  Y + (size_t)(m0 + row) * CDIM + k0 + col);
        }
#pragma unroll
        for (int p = 0; p < 4; ++p) {
            int id = p * 256 + tid;
            int row = id >> 3, col = (id & 7) * 4;
            cpa16(bb + (row * PJ_LD + col) * 4,
                  w + (size_t)(o0 + row) * CDIM + k0 + col);
        }
        cpa_commit();
    };

    load_tiles(0, 0);
    load_tiles(1, 1);
    for (int it = 0; it < 24; ++it) {
        if (it == 23) cpa_wait<0>(); else cpa_wait<1>();
        __syncthreads();
        if (it + 2 < 24) load_tiles(it + 2, (it + 2) % 3);

        uint32_t ab = pb + ((it % 3) * PJ_STAGE_W) * 4;

        // fragment double-buffering: prefetch s+1 while issuing s's mmas
        uint32_t af[2][4][4], bfb[2][2][4];
        ldsm4(bfb[0][0], ab + (boff0)*4);
        ldsm4(bfb[0][1], ab + (boff1)*4);
#pragma unroll
        for (int mt = 0; mt < 4; ++mt) ldsm4(af[0][mt], ab + (aoff[mt]) * 4);

#pragma unroll
        for (int s = 0; s < 4; ++s) {
            int cur = s & 1;
            if (s < 3) {
                int nx = cur ^ 1;
                ldsm4(bfb[nx][0], ab + (boff0 + (s + 1) * 8) * 4);
                ldsm4(bfb[nx][1], ab + (boff1 + (s + 1) * 8) * 4);
#pragma unroll
                for (int mt = 0; mt < 4; ++mt)
                    ldsm4(af[nx][mt], ab + (aoff[mt] + (s + 1) * 8) * 4);
            }
#pragma unroll
            for (int mt = 0; mt < 4; ++mt)
#pragma unroll
                for (int p = 0; p < 2; ++p) {
                    mma8(acc[mt][2 * p],     af[cur][mt], bfb[cur][p][0], bfb[cur][p][1]);
                    mma8(acc[mt][2 * p + 1], af[cur][mt], bfb[cur][p][2], bfb[cur][p][3]);
                }
        }
    }

    // epilogue: bias + store (row -> (b, q))
#pragma unroll
    for (int mt = 0; mt < 4; ++mt)
#pragma unroll
        for (int nt = 0; nt < 4; ++nt) {
            int gr = m0 + warp_m * 64 + mt * 16 + grp;
            int o  = o0 + warp_n * 32 + nt * 8 + 2 * qd;
            float bv0 = bias[o], bv1 = bias[o + 1];
            int b0i = gr >> 6, q0 = gr & 63;
            int b1i = (gr + 8) >> 6, q1 = (gr + 8) & 63;
            float2 v0 = make_float2(acc[mt][nt][0] + bv0, acc[mt][nt][1] + bv1);
            float2 v1 = make_float2(acc[mt][nt][2] + bv0, acc[mt][nt][3] + bv1);
            *(float2*)&out[(size_t)b0i * NTOK * CDIM + (size_t)q0 * CDIM + o] = v0;
            *(float2*)&out[(size_t)b1i * NTOK * CDIM + (size_t)q1 * CDIM + o] = v1;
        }
}

extern "C" void kernel_launch(void* const* d_in, const int* in_sizes, int n_in,
                              void* d_out, int out_size) {
    const float* x    = (const float*)d_in[0];
    const float* w    = (const float*)d_in[1];
    const float* bias = (const float*)d_in[2];
    float* out = (float*)d_out;

    size_t smemA = (size_t)SMEM_WORDS * sizeof(float);  // 99328 B
    cudaFuncSetAttribute(attn_k, cudaFuncAttributeMaxDynamicSharedMemorySize, (int)smemA);
    attn_k<<<BATCH, 256, smemA>>>(x, out);

    size_t smemP = (size_t)(3 * PJ_STAGE_W) * sizeof(uint32_t);  // 110592 B
    cudaFuncSetAttribute(proj_k, cudaFuncAttributeMaxDynamicSharedMemorySize, (int)smemP);
    proj_k<<<dim3(6, 128), 256, smemP>>>(w, bias, out);
}

// round 8
// speedup vs baseline: 1.4023x; 1.0609x over previous
#include <cuda_runtime.h>
#include <cstdint>

#define BATCH 256
#define NTOK  320
#define CDIM  768
#define LZ    64
#define LK    256
#define SCALE 0.125f

// Scratch: O transposed per batch; flat == Y_all (16384 x 768) row-major.
__device__ float g_OT[(size_t)BATCH * CDIM * LZ];

__device__ __forceinline__ uint32_t f2t(float x) {
    uint32_t r;
    asm("cvt.rna.tf32.f32 %0, %1;" : "=r"(r) : "f"(x));
    return r;
}

__device__ __forceinline__ void mma8(float* d, const uint32_t* a,
                                     uint32_t b0, uint32_t b1) {
    asm volatile(
        "mma.sync.aligned.m16n8k8.row.col.f32.tf32.tf32.f32 "
        "{%0,%1,%2,%3}, {%4,%5,%6,%7}, {%8,%9}, {%0,%1,%2,%3};\n"
        : "+f"(d[0]), "+f"(d[1]), "+f"(d[2]), "+f"(d[3])
        : "r"(a[0]), "r"(a[1]), "r"(a[2]), "r"(a[3]), "r"(b0), "r"(b1));
}

__device__ __forceinline__ void ldsm4(uint32_t* r, uint32_t saddr) {
    asm volatile("ldmatrix.sync.aligned.m8n8.x4.shared.b16 {%0,%1,%2,%3}, [%4];"
                 : "=r"(r[0]), "=r"(r[1]), "=r"(r[2]), "=r"(r[3]) : "r"(saddr));
}

__device__ __forceinline__ void cpa16(uint32_t saddr, const void* gaddr) {
    asm volatile("cp.async.cg.shared.global [%0], [%1], 16;\n"
                 :: "r"(saddr), "l"(gaddr));
}
__device__ __forceinline__ void cpa_commit() {
    asm volatile("cp.async.commit_group;\n");
}
template <int N>
__device__ __forceinline__ void cpa_wait() {
    asm volatile("cp.async.wait_group %0;\n" :: "n"(N));
}

// ---------------- fused attention per batch (256 threads, occ 2, single wave) ----------------
#define P1_LD  36
#define SS_LD  260
#define K2_LD  40    // %32==8 -> scalar B loads conflict-free (bank=8*qd+grp)
#define STG_LD 68

#define STAGE_W 11520
#define SMEM_WORDS 24832                   // 99328 B -> occ 2
#define K2_BUF_W 10240
#define STG_OFF  20480

extern __shared__ float smem[];

__global__ __launch_bounds__(256, 2) void attn_k(const float* __restrict__ x) {
    float*    sS  = smem;                     // 64 x 260 (time-muxed region)
    uint32_t* sSu = (uint32_t*)smem;
    uint32_t* pool = (uint32_t*)smem;
    float*    stage = smem + STG_OFF;         // phase 2: 2 x (32 x 68)

    const uint32_t ssb   = (uint32_t)__cvta_generic_to_shared(sS);
    const uint32_t poolb = ssb;

    const int b    = blockIdx.x;
    const int tid  = threadIdx.x;
    const int wid  = tid >> 5;
    const int lane = tid & 31;
    const int grp  = lane >> 2;
    const int qd   = lane & 3;
    const float* xb = x + (size_t)b * NTOK * CDIM;
    const float* Kb = xb + LZ * CDIM;

    const int lrow  = lane & 15;
    const int lcolw = (lane >> 4) * 4;
    const int brow  = (lane & 7) + ((lane >> 4) << 3);
    const int bcolw = ((lane >> 3) & 1) * 4;

    // ---------- Phase 1: S = Q K^T * scale ----------
    const int warp_m = wid >> 2;
    const int warp_n = wid & 3;

    const int aoff0 = (warp_m * 32 + 0  + lrow) * P1_LD + lcolw;
    const int aoff1 = (warp_m * 32 + 16 + lrow) * P1_LD + lcolw;
    int boff[4];
#pragma unroll
    for (int nt2 = 0; nt2 < 4; ++nt2)
        boff[nt2] = (warp_n * 64 + nt2 * 16 + brow) * P1_LD + bcolw;

    float acc[2][8][4];
#pragma unroll
    for (int i = 0; i < 2; ++i)
#pragma unroll
        for (int j = 0; j < 8; ++j)
#pragma unroll
            for (int r = 0; r < 4; ++r) acc[i][j][r] = 0.0f;

    auto load_tiles = [&](int it, int st) {
        int c0 = it * 32;
        uint32_t qb = poolb + (st * STAGE_W) * 4;
        uint32_t kb = qb + 2304 * 4;
#pragma unroll
        for (int p = 0; p < 2; ++p) {
            int id = p * 256 + tid;
            int row = id >> 3, col = (id & 7) * 4;
            cpa16(qb + (row * P1_LD + col) * 4, xb + row * CDIM + c0 + col);
        }
#pragma unroll
        for (int p = 0; p < 8; ++p) {
            int id = p * 256 + tid;
            int row = id >> 3, col = (id & 7) * 4;
            cpa16(kb + (row * P1_LD + col) * 4, Kb + row * CDIM + c0 + col);
        }
        cpa_commit();
    };

    load_tiles(0, 0);
    for (int it = 0; it < 24; ++it) {
        cpa_wait<0>();
        __syncthreads();
        if (it + 1 < 24) load_tiles(it + 1, (it + 1) & 1);

        uint32_t qb = poolb + ((it & 1) * STAGE_W) * 4;
        uint32_t kb = qb + 2304 * 4;
#pragma unroll
        for (int s = 0; s < 4; ++s) {
            uint32_t a[2][4], bf[4][4];
            ldsm4(a[0], qb + (aoff0 + s * 8) * 4);
            ldsm4(a[1], qb + (aoff1 + s * 8) * 4);
#pragma unroll
            for (int nt2 = 0; nt2 < 4; ++nt2)
                ldsm4(bf[nt2], kb + (boff[nt2] + s * 8) * 4);
#pragma unroll
            for (int nt2 = 0; nt2 < 4; ++nt2)
#pragma unroll
                for (int mt = 0; mt < 2; ++mt) {
                    mma8(acc[mt][2 * nt2],     a[mt], bf[nt2][0], bf[nt2][1]);
                    mma8(acc[mt][2 * nt2 + 1], a[mt], bf[nt2][2], bf[nt2][3]);
                }
        }
    }
    __syncthreads();

    // store S (scaled)
#pragma unroll
    for (int mt = 0; mt < 2; ++mt)
#pragma unroll
        for (int nt = 0; nt < 8; ++nt) {
            int r = warp_m * 32 + mt * 16 + grp;
            int c = warp_n * 64 + nt * 8 + 2 * qd;
            sS[r * SS_LD + c]           = acc[mt][nt][0] * SCALE;
            sS[r * SS_LD + c + 1]       = acc[mt][nt][1] * SCALE;
            sS[(r + 8) * SS_LD + c]     = acc[mt][nt][2] * SCALE;
            sS[(r + 8) * SS_LD + c + 1] = acc[mt][nt][3] * SCALE;
        }
    __syncthreads();

    // ---------- softmax ----------
#pragma unroll
    for (int r = 0; r < 8; ++r) {
        int q = wid * 8 + r;
        float* row = sS + q * SS_LD;
        uint32_t* rowu = sSu + q * SS_LD;
        float v[8];
        float mx = -1e30f;
#pragma unroll
        for (int m = 0; m < 8; ++m) {
            v[m] = row[lane + 32 * m];
            mx = fmaxf(mx, v[m]);
        }
#pragma unroll
        for (int s = 16; s > 0; s >>= 1)
            mx = fmaxf(mx, __shfl_xor_sync(0xffffffffu, mx, s));
        float sum = 0.0f;
#pragma unroll
        for (int m = 0; m < 8; ++m) {
            v[m] = __expf(v[m] - mx);
            sum += v[m];
        }
#pragma unroll
        for (int s = 16; s > 0; s >>= 1)
            sum += __shfl_xor_sync(0xffffffffu, sum, s);
        float inv = 1.0f / sum;
#pragma unroll
        for (int m = 0; m < 8; ++m) rowu[lane + 32 * m] = f2t(v[m] * inv);
    }
    __syncthreads();

    // ---------- P fragments register-resident ----------
    const int warp_m2 = wid & 3;
    const int kg      = wid >> 2;

    uint32_t aP[16][4];
#pragma unroll
    for (int ks = 0; ks < 16; ++ks)
        ldsm4(aP[ks], ssb + ((warp_m2 * 16 + lrow) * SS_LD +
                             kg * 128 + ks * 8 + lcolw) * 4);
    __syncthreads();

    // ---------- Phase 2: O^T in 24 c-chunks of 32 (pure MMA loop) ----------
    const uint32_t k2b0 = poolb;
    const uint32_t k2b1 = poolb + K2_BUF_W * 4;
    uint32_t* sK2[2] = { pool, pool + K2_BUF_W };

    auto load_k2 = [&](int it, int st) {
        int c0 = it * 32;
        uint32_t kb = st ? k2b1 : k2b0;
#pragma unroll
        for (int p = 0; p < 8; ++p) {
            int id = p * 256 + tid;
            int row = id >> 3, col = (id & 7) * 4;
            cpa16(kb + (row * K2_LD + col) * 4, Kb + row * CDIM + c0 + col);
        }
        cpa_commit();
    };

    float* stg = stage + kg * (32 * STG_LD);

    load_k2(0, 0);
    for (int it = 0; it < 24; ++it) {
        int c0 = it * 32;
        cpa_wait<0>();
        __syncthreads();
        if (it + 1 < 24) load_k2(it + 1, (it + 1) & 1);

        uint32_t* K2 = sK2[it & 1];

        float acc2[4][4];
#pragma unroll
        for (int i = 0; i < 4; ++i)
#pragma unroll
            for (int r = 0; r < 4; ++r) acc2[i][r] = 0.0f;

#pragma unroll
        for (int ks = 0; ks < 16; ++ks) {
            int kq = kg * 128 + ks * 8 + qd;
#pragma unroll
            for (int nt = 0; nt < 4; ++nt) {
                int nb = nt * 8 + grp;
                uint32_t b0 = K2[kq * K2_LD + nb];
                uint32_t b1 = K2[(kq + 4) * K2_LD + nb];
                mma8(acc2[nt], aP[ks], b0, b1);
            }
        }

        // stage partials transposed [c_local][t]
#pragma unroll
        for (int nt = 0; nt < 4; ++nt) {
            int cc = nt * 8 + 2 * qd;
            int rq = warp_m2 * 16 + grp;
            stg[cc * STG_LD + rq]           = acc2[nt][0];
            stg[(cc + 1) * STG_LD + rq]     = acc2[nt][1];
            stg[cc * STG_LD + rq + 8]       = acc2[nt][2];
            stg[(cc + 1) * STG_LD + rq + 8] = acc2[nt][3];
        }
        __syncthreads();

        // reduce 2 k-halves, write 32x64 O^T chunk
        float* dst = g_OT + (size_t)b * CDIM * LZ + (size_t)c0 * LZ;
#pragma unroll
        for (int p = 0; p < 2; ++p) {
            int fid = p * 256 + tid;
            int row = fid >> 4, c4 = (fid & 15) * 4;
            float4 s0 = *(float4*)&stage[row * STG_LD + c4];
            float4 s1 = *(float4*)&stage[32 * STG_LD + row * STG_LD + c4];
            float4 o;
            o.x = s0.x + s1.x; o.y = s0.y + s1.y;
            o.z = s0.z + s1.z; o.w = s0.w + s1.w;
            *(float4*)&dst[row * LZ + c4] = o;
        }
    }
}

// ---------------- projection GEMM + fused concat-tail copy ----------------
#define PJ_LD 36
#define PJ_STAGE_W (2 * 128 * PJ_LD)   // 9216 words
extern __shared__ uint32_t psmem[];

__global__ __launch_bounds__(256, 2) void proj_k(const float* __restrict__ x,
                                                 const float* __restrict__ w,
                                                 const float* __restrict__ bias,
                                                 float* __restrict__ out) {
    const int o0 = blockIdx.x * 128;
    const int m0 = blockIdx.y * 128;
    const float* Y = g_OT;
    const int tid  = threadIdx.x;
    const int wid  = tid >> 5;
    const int lane = tid & 31;
    const int grp  = lane >> 2;
    const int qd   = lane & 3;
    const int warp_m = wid >> 2;
    const int warp_n = wid & 3;

    const uint32_t pb = (uint32_t)__cvta_generic_to_shared(psmem);

    const int lrow  = lane & 15;
    const int lcolw = (lane >> 4) * 4;
    const int brow  = (lane & 7) + ((lane >> 4) << 3);
    const int bcolw = ((lane >> 3) & 1) * 4;

    int aoff[4], boff0, boff1;
#pragma unroll
    for (int mt = 0; mt < 4; ++mt)
        aoff[mt] = (warp_m * 64 + mt * 16 + lrow) * PJ_LD + lcolw;
    boff0 = (128 * PJ_LD) + (warp_n * 32 + 0  + brow) * PJ_LD + bcolw;
    boff1 = (128 * PJ_LD) + (warp_n * 32 + 16 + brow) * PJ_LD + bcolw;

    float acc[4][4][4];
#pragma unroll
    for (int i = 0; i < 4; ++i)
#pragma unroll
        for (int j = 0; j < 4; ++j)
#pragma unroll
            for (int r = 0; r < 4; ++r) acc[i][j][r] = 0.0f;

    // ---- fused tail-copy: 768 CTAs x 16384 float4 = 256 batches x 49152 ----
    const int cta_id = blockIdx.y * 6 + blockIdx.x;  // 0..767
    const long copy_base = (long)cta_id * 16384;
    const float4* x4 = (const float4*)x;
    float4* o4 = (float4*)out;

    auto copy_chunk = [&](int i) {  // i in 0..15: 1024 float4 per call (4/thread)
#pragma unroll
        for (int p = 0; p < 4; ++p) {
            long gi = copy_base + (long)i * 1024 + p * 256 + tid;
            int bb = (int)(gi / 49152);           // float4 per batch-tail
            int rr = (int)(gi - (long)bb * 49152);
            long off = (long)bb * 61440 + 12288 + rr;  // batch stride, skip LZ rows
            o4[off] = x4[off];
        }
    };

    auto load_tiles = [&](int it, int st) {
        int k0 = it * 32;
        uint32_t ab = pb + (st * PJ_STAGE_W) * 4;
        uint32_t bb = ab + (128 * PJ_LD) * 4;
#pragma unroll
        for (int p = 0; p < 4; ++p) {
            int id = p * 256 + tid;
            int row = id >> 3, col = (id & 7) * 4;
            cpa16(ab + (row * PJ_LD + col) * 4,
                  Y + (size_t)(m0 + row) * CDIM + k0 + col);
        }
#pragma unroll
        for (int p = 0; p < 4; ++p) {
            int id = p * 256 + tid;
            int row = id >> 3, col = (id & 7) * 4;
            cpa16(bb + (row * PJ_LD + col) * 4,
                  w + (size_t)(o0 + row) * CDIM + k0 + col);
        }
        cpa_commit();
    };

    load_tiles(0, 0);
    load_tiles(1, 1);
    for (int it = 0; it < 24; ++it) {
        if (it == 23) cpa_wait<0>(); else cpa_wait<1>();
        __syncthreads();
        if (it + 2 < 24) load_tiles(it + 2, (it + 2) % 3);
        if (it < 16) copy_chunk(it);  // interleaved tail copy (DRAM overlap)

        uint32_t ab = pb + ((it % 3) * PJ_STAGE_W) * 4;
#pragma unroll
        for (int s = 0; s < 4; ++s) {
            uint32_t a[4][4], bf[2][4];
            ldsm4(bf[0], ab + (boff0 + s * 8) * 4);
            ldsm4(bf[1], ab + (boff1 + s * 8) * 4);
#pragma unroll
            for (int mt = 0; mt < 4; ++mt)
                ldsm4(a[mt], ab + (aoff[mt] + s * 8) * 4);
#pragma unroll
            for (int mt = 0; mt < 4; ++mt)
#pragma unroll
                for (int p = 0; p < 2; ++p) {
                    mma8(acc[mt][2 * p],     a[mt], bf[p][0], bf[p][1]);
                    mma8(acc[mt][2 * p + 1], a[mt], bf[p][2], bf[p][3]);
                }
        }
    }

    // epilogue: bias + store (row -> (b, q))
#pragma unroll
    for (int mt = 0; mt < 4; ++mt)
#pragma unroll
        for (int nt = 0; nt < 4; ++nt) {
            int gr = m0 + warp_m * 64 + mt * 16 + grp;
            int o  = o0 + warp_n * 32 + nt * 8 + 2 * qd;
            float bv0 = bias[o], bv1 = bias[o + 1];
            int b0i = gr >> 6, q0 = gr & 63;
            int b1i = (gr + 8) >> 6, q1 = (gr + 8) & 63;
            float2 v0 = make_float2(acc[mt][nt][0] + bv0, acc[mt][nt][1] + bv1);
            float2 v1 = make_float2(acc[mt][nt][2] + bv0, acc[mt][nt][3] + bv1);
            *(float2*)&out[(size_t)b0i * NTOK * CDIM + (size_t)q0 * CDIM + o] = v0;
            *(float2*)&out[(size_t)b1i * NTOK * CDIM + (size_t)q1 * CDIM + o] = v1;
        }
}

extern "C" void kernel_launch(void* const* d_in, const int* in_sizes, int n_in,
                              void* d_out, int out_size) {
    const float* x    = (const float*)d_in[0];
    const float* w    = (const float*)d_in[1];
    const float* bias = (const float*)d_in[2];
    float* out = (float*)d_out;

    size_t smemA = (size_t)SMEM_WORDS * sizeof(float);  // 99328 B
    cudaFuncSetAttribute(attn_k, cudaFuncAttributeMaxDynamicSharedMemorySize, (int)smemA);
    attn_k<<<BATCH, 256, smemA>>>(x);

    size_t smemP = (size_t)(3 * PJ_STAGE_W) * sizeof(uint32_t);  // 110592 B
    cudaFuncSetAttribute(proj_k, cudaFuncAttributeMaxDynamicSharedMemorySize, (int)smemP);
    proj_k<<<dim3(6, 128), 256, smemP>>>(x, w, bias, out);
}

// round 10
// speedup vs baseline: 1.6719x; 1.1922x over previous
#include <cuda_runtime.h>
#include <cuda_fp16.h>
#include <cstdint>

#define BATCH 256
#define NTOK  320
#define CDIM  768
#define LZ    64
#define LK    256
#define SCALE 0.125f

__device__ __half g_Xh[(size_t)BATCH * NTOK * CDIM];   // fp16 copy of x
__device__ __half g_Wh[(size_t)CDIM * CDIM];           // fp16 copy of proj_w
__device__ __half g_OTh[(size_t)BATCH * CDIM * LZ];    // O^T fp16; flat == Y_all(16384x768)

__device__ __forceinline__ void mma16(float* d, const uint32_t* a,
                                      uint32_t b0, uint32_t b1) {
    asm volatile(
        "mma.sync.aligned.m16n8k16.row.col.f32.f16.f16.f32 "
        "{%0,%1,%2,%3}, {%4,%5,%6,%7}, {%8,%9}, {%0,%1,%2,%3};\n"
        : "+f"(d[0]), "+f"(d[1]), "+f"(d[2]), "+f"(d[3])
        : "r"(a[0]), "r"(a[1]), "r"(a[2]), "r"(a[3]), "r"(b0), "r"(b1));
}
__device__ __forceinline__ void ldsm4(uint32_t* r, uint32_t saddr) {
    asm volatile("ldmatrix.sync.aligned.m8n8.x4.shared.b16 {%0,%1,%2,%3}, [%4];"
                 : "=r"(r[0]), "=r"(r[1]), "=r"(r[2]), "=r"(r[3]) : "r"(saddr));
}
__device__ __forceinline__ void ldsm4t(uint32_t* r, uint32_t saddr) {
    asm volatile("ldmatrix.sync.aligned.m8n8.x4.trans.shared.b16 {%0,%1,%2,%3}, [%4];"
                 : "=r"(r[0]), "=r"(r[1]), "=r"(r[2]), "=r"(r[3]) : "r"(saddr));
}
__device__ __forceinline__ void cpa16(uint32_t saddr, const void* gaddr) {
    asm volatile("cp.async.cg.shared.global [%0], [%1], 16;\n"
                 :: "r"(saddr), "l"(gaddr));
}
__device__ __forceinline__ void cpa_commit() {
    asm volatile("cp.async.commit_group;\n");
}
template <int N>
__device__ __forceinline__ void cpa_wait() {
    asm volatile("cp.async.wait_group %0;\n" :: "n"(N));
}

// ---------------- convert pass: x->fp16, W->fp16, exact fp32 tail copy ----------------
__device__ __forceinline__ uint2 f4h(float4 v) {
    __half2 a = __floats2half2_rn(v.x, v.y);
    __half2 b = __floats2half2_rn(v.z, v.w);
    uint2 r;
    r.x = *(uint32_t*)&a;
    r.y = *(uint32_t*)&b;
    return r;
}

__global__ void conv_k(const float4* __restrict__ x4, const float4* __restrict__ w4,
                       float4* __restrict__ o4) {
    const int WCH = CDIM * CDIM / 4;                 // 147456
    const int XCH = BATCH * NTOK * CDIM / 4;         // 15728640
    uint2* xh2 = (uint2*)g_Xh;
    uint2* wh2 = (uint2*)g_Wh;
    for (long i = blockIdx.x * blockDim.x + threadIdx.x; i < WCH + XCH;
         i += (long)gridDim.x * blockDim.x) {
        if (i < WCH) {
            float4 v = w4[i];
            wh2[i] = f4h(v);
        } else {
            long j = i - WCH;
            float4 v = x4[j];
            xh2[j] = f4h(v);
            int tok = (int)((j / 192) % 320);
            if (tok >= LZ) o4[j] = v;   // exact concat tail
        }
    }
}

// ---------------- fused attention per batch (fp16 tensor cores) ----------------
#define P1_LDH 40    // halves; 80B row => conflict-free ldsm
#define SS_LD  260   // fp32 words
#define PS_LDH 264   // halves; 528B row => conflict-free ldsm
#define K2_LDH 40
#define STG_LD 68    // fp32 words

// byte layout (time-multiplexed):
//   phase1: 2 stages x (Q 64x40h=5120B + K 256x40h=20480B)=25600B -> [0,51200)
//   softmax: sP halves [0,33792) ; sS fp32 [34048,100608)
//   phase2: K2 2 x 20480 [0,40960) ; stage 2x32x68x4 [40960,58368)
#define AT_SMEM 100608

extern __shared__ char smemc[];

__global__ __launch_bounds__(256, 2) void attn_k() {
    float*  sS = (float*)(smemc + 34048);
    __half* sP = (__half*)smemc;
    float*  stage = (float*)(smemc + 40960);
    uint32_t sb;
    asm("{ .reg .u64 t; cvta.to.shared.u64 t, %1; cvt.u32.u64 %0, t; }"
        : "=r"(sb) : "l"(smemc));

    const int b    = blockIdx.x;
    const int tid  = threadIdx.x;
    const int wid  = tid >> 5;
    const int lane = tid & 31;
    const int grp  = lane >> 2;
    const int qd   = lane & 3;
    const __half* xhb = g_Xh + (size_t)b * NTOK * CDIM;
    const __half* xhK = xhb + LZ * CDIM;

    const int lrow  = lane & 15;
    const int lcolh = (lane >> 4) * 8;
    const int brow  = (lane & 7) + ((lane >> 4) << 3);
    const int bcolh = ((lane >> 3) & 1) * 8;

    // ---------- Phase 1: S = Q K^T * scale (M=64, N=256, red=768) ----------
    const int warp_m = wid >> 2;   // 0..1 -> 32 rows
    const int warp_n = wid & 3;    // 0..3 -> 64 cols

    float acc[2][8][4];
#pragma unroll
    for (int i = 0; i < 2; ++i)
#pragma unroll
        for (int j = 0; j < 8; ++j)
#pragma unroll
            for (int r = 0; r < 4; ++r) acc[i][j][r] = 0.0f;

    auto load_tiles = [&](int it, int st) {
        int c0 = it * 32;
        uint32_t qb = sb + st * 25600;
        uint32_t kb = qb + 5120;
        {   // Q 64x32h = 256 chunks, 1/thread
            int row = tid >> 2, kc = (tid & 3) * 8;
            cpa16(qb + row * 80 + kc * 2, xhb + row * CDIM + c0 + kc);
        }
#pragma unroll
        for (int p = 0; p < 4; ++p) {  // K 256x32h = 1024 chunks, 4/thread
            int id = p * 256 + tid;
            int row = id >> 2, kc = (id & 3) * 8;
            cpa16(kb + row * 80 + kc * 2, xhK + row * CDIM + c0 + kc);
        }
        cpa_commit();
    };

    load_tiles(0, 0);
    for (int it = 0; it < 24; ++it) {
        cpa_wait<0>();
        __syncthreads();
        if (it + 1 < 24) load_tiles(it + 1, (it + 1) & 1);

        uint32_t qb = sb + (it & 1) * 25600;
        uint32_t kb = qb + 5120;
#pragma unroll
        for (int s = 0; s < 2; ++s) {
            uint32_t a[2][4], bf[4][4];
            ldsm4(a[0], qb + ((warp_m * 32 + lrow) * P1_LDH + s * 16 + lcolh) * 2);
            ldsm4(a[1], qb + ((warp_m * 32 + 16 + lrow) * P1_LDH + s * 16 + lcolh) * 2);
#pragma unroll
            for (int nt2 = 0; nt2 < 4; ++nt2)
                ldsm4(bf[nt2],
                      kb + ((warp_n * 64 + nt2 * 16 + brow) * P1_LDH + s * 16 + bcolh) * 2);
#pragma unroll
            for (int nt2 = 0; nt2 < 4; ++nt2)
#pragma unroll
                for (int mt = 0; mt < 2; ++mt) {
                    mma16(acc[mt][2 * nt2],     a[mt], bf[nt2][0], bf[nt2][1]);
                    mma16(acc[mt][2 * nt2 + 1], a[mt], bf[nt2][2], bf[nt2][3]);
                }
        }
    }
    __syncthreads();  // phase-1 buffers dead; region becomes sS

    // store S (scaled) fp32
#pragma unroll
    for (int mt = 0; mt < 2; ++mt)
#pragma unroll
        for (int nt = 0; nt < 8; ++nt) {
            int r = warp_m * 32 + mt * 16 + grp;
            int c = warp_n * 64 + nt * 8 + 2 * qd;
            sS[r * SS_LD + c]           = acc[mt][nt][0] * SCALE;
            sS[r * SS_LD + c + 1]       = acc[mt][nt][1] * SCALE;
            sS[(r + 8) * SS_LD + c]     = acc[mt][nt][2] * SCALE;
            sS[(r + 8) * SS_LD + c + 1] = acc[mt][nt][3] * SCALE;
        }
    __syncthreads();

    // ---------- softmax (8 warps x 8 rows); probs -> fp16 sP ----------
#pragma unroll
    for (int r = 0; r < 8; ++r) {
        int q = wid * 8 + r;
        float* row = sS + q * SS_LD;
        __half* rowp = sP + q * PS_LDH;
        float v[8];
        float mx = -1e30f;
#pragma unroll
        for (int m = 0; m < 8; ++m) {
            v[m] = row[lane + 32 * m];
            mx = fmaxf(mx, v[m]);
        }
#pragma unroll
        for (int s = 16; s > 0; s >>= 1)
            mx = fmaxf(mx, __shfl_xor_sync(0xffffffffu, mx, s));
        float sum = 0.0f;
#pragma unroll
        for (int m = 0; m < 8; ++m) {
            v[m] = __expf(v[m] - mx);
            sum += v[m];
        }
#pragma unroll
        for (int s = 16; s > 0; s >>= 1)
            sum += __shfl_xor_sync(0xffffffffu, sum, s);
        float inv = 1.0f / sum;
#pragma unroll
        for (int m = 0; m < 8; ++m)
            rowp[lane + 32 * m] = __float2half_rn(v[m] * inv);
    }
    __syncthreads();

    // ---------- P fragments register-resident (8 k16-frags per warp) ----------
    const int warp_m2 = wid & 3;   // 16 rows
    const int kg      = wid >> 2;  // k half: [kg*128, kg*128+128)

    uint32_t aP[8][4];
#pragma unroll
    for (int ks = 0; ks < 8; ++ks)
        ldsm4(aP[ks], sb + ((warp_m2 * 16 + lrow) * PS_LDH +
                            kg * 128 + ks * 16 + lcolh) * 2);
    __syncthreads();  // sP consumed; region becomes K2 buffers

    // ---------- Phase 2: O^T in 24 c-chunks of 32 ----------
    const int tkrow = (lane & 7) + ((lane >> 3) & 1) * 8;  // trans-ldsm k row
    const int tnblk = (lane >> 4) * 8;                     // trans-ldsm n chunk

    auto load_k2 = [&](int it, int st) {
        int c0 = it * 32;
        uint32_t kb = sb + st * 20480;
#pragma unroll
        for (int p = 0; p < 4; ++p) {  // 256x32h = 1024 chunks, 4/thread
            int id = p * 256 + tid;
            int row = id >> 2, cc = (id & 3) * 8;
            cpa16(kb + row * 80 + cc * 2, xhK + row * CDIM + c0 + cc);
        }
        cpa_commit();
    };

    float* stg = stage + kg * (32 * STG_LD);

    load_k2(0, 0);
    for (int it = 0; it < 24; ++it) {
        int c0 = it * 32;
        cpa_wait<0>();
        __syncthreads();
        if (it + 1 < 24) load_k2(it + 1, (it + 1) & 1);

        uint32_t kb = sb + (it & 1) * 20480;

        float acc2[4][4];
#pragma unroll
        for (int i = 0; i < 4; ++i)
#pragma unroll
            for (int r = 0; r < 4; ++r) acc2[i][r] = 0.0f;

#pragma unroll
        for (int ks = 0; ks < 8; ++ks) {
            int kbase = kg * 128 + ks * 16;
            uint32_t bt[2][4];
#pragma unroll
            for (int h = 0; h < 2; ++h)
                ldsm4t(bt[h], kb + ((kbase + tkrow) * K2_LDH + h * 16 + tnblk) * 2);
            mma16(acc2[0], aP[ks], bt[0][0], bt[0][1]);
            mma16(acc2[1], aP[ks], bt[0][2], bt[0][3]);
            mma16(acc2[2], aP[ks], bt[1][0], bt[1][1]);
            mma16(acc2[3], aP[ks], bt[1][2], bt[1][3]);
        }

        // stage partials transposed [c_local][t]
#pragma unroll
        for (int nt = 0; nt < 4; ++nt) {
            int cc = nt * 8 + 2 * qd;
            int rq = warp_m2 * 16 + grp;
            stg[cc * STG_LD + rq]           = acc2[nt][0];
            stg[(cc + 1) * STG_LD + rq]     = acc2[nt][1];
            stg[cc * STG_LD + rq + 8]       = acc2[nt][2];
            stg[(cc + 1) * STG_LD + rq + 8] = acc2[nt][3];
        }
        __syncthreads();

        // reduce 2 k-halves, convert to fp16, write 32x64 O^T chunk
        {
            int row = tid >> 3, c8 = (tid & 7) * 8;
            float4 s0a = *(float4*)&stage[row * STG_LD + c8];
            float4 s0b = *(float4*)&stage[row * STG_LD + c8 + 4];
            float4 s1a = *(float4*)&stage[32 * STG_LD + row * STG_LD + c8];
            float4 s1b = *(float4*)&stage[32 * STG_LD + row * STG_LD + c8 + 4];
            float4 oa, ob;
            oa.x = s0a.x + s1a.x; oa.y = s0a.y + s1a.y;
            oa.z = s0a.z + s1a.z; oa.w = s0a.w + s1a.w;
            ob.x = s0b.x + s1b.x; ob.y = s0b.y + s1b.y;
            ob.z = s0b.z + s1b.z; ob.w = s0b.w + s1b.w;
            uint2 ha = f4h(oa), hb = f4h(ob);
            uint4 pk = make_uint4(ha.x, ha.y, hb.x, hb.y);
            *(uint4*)(g_OTh + (size_t)b * CDIM * LZ + (size_t)(c0 + row) * LZ + c8) = pk;
        }
    }
}

// ---------------- projection: Y_all(16384x768)h @ Wh^T + bias ----------------
#define PJ_LDH 40
#define PJ_STAGE_B 20480    // A 128x40h + B 128x40h bytes
#define PJ_SMEM (3 * PJ_STAGE_B)

extern __shared__ char psmemc[];

__global__ __launch_bounds__(256, 2) void proj_k(const float* __restrict__ bias,
                                                 float* __restrict__ out) {
    const int o0 = blockIdx.x * 128;
    const int m0 = blockIdx.y * 128;
    const int tid  = threadIdx.x;
    const int wid  = tid >> 5;
    const int lane = tid & 31;
    const int grp  = lane >> 2;
    const int qd   = lane & 3;
    const int warp_m = wid >> 2;  // 0..1 -> 64 rows
    const int warp_n = wid & 3;   // 0..3 -> 32 cols

    uint32_t pb;
    asm("{ .reg .u64 t; cvta.to.shared.u64 t, %1; cvt.u32.u64 %0, t; }"
        : "=r"(pb) : "l"(psmemc));

    const int lrow  = lane & 15;
    const int lcolh = (lane >> 4) * 8;
    const int brow  = (lane & 7) + ((lane >> 4) << 3);
    const int bcolh = ((lane >> 3) & 1) * 8;

    float acc[4][4][4];
#pragma unroll
    for (int i = 0; i < 4; ++i)
#pragma unroll
        for (int j = 0; j < 4; ++j)
#pragma unroll
            for (int r = 0; r < 4; ++r) acc[i][j][r] = 0.0f;

    auto load_tiles = [&](int it, int st) {
        int k0 = it * 32;
        uint32_t ab = pb + st * PJ_STAGE_B;
        uint32_t bb = ab + 10240;
#pragma unroll
        for (int p = 0; p < 2; ++p) {  // A: 128x32h = 512 chunks
            int id = p * 256 + tid;
            int row = id >> 2, kc = (id & 3) * 8;
            cpa16(ab + row * 80 + kc * 2, g_OTh + (size_t)(m0 + row) * CDIM + k0 + kc);
        }
#pragma unroll
        for (int p = 0; p < 2; ++p) {  // B: 128x32h
            int id = p * 256 + tid;
            int row = id >> 2, kc = (id & 3) * 8;
            cpa16(bb + row * 80 + kc * 2, g_Wh + (size_t)(o0 + row) * CDIM + k0 + kc);
        }
        cpa_commit();
    };

    load_tiles(0, 0);
    load_tiles(1, 1);
    for (int it = 0; it < 24; ++it) {
        if (it == 23) cpa_wait<0>(); else cpa_wait<1>();
        __syncthreads();
        if (it + 2 < 24) load_tiles(it + 2, (it + 2) % 3);

        uint32_t ab = pb + (it % 3) * PJ_STAGE_B;
        uint32_t bb = ab + 10240;
#pragma unroll
        for (int s = 0; s < 2; ++s) {
            uint32_t a[4][4], bf[2][4];
            ldsm4(bf[0], bb + ((warp_n * 32 + brow) * PJ_LDH + s * 16 + bcolh) * 2);
            ldsm4(bf[1], bb + ((warp_n * 32 + 16 + brow) * PJ_LDH + s * 16 + bcolh) * 2);
#pragma unroll
            for (int mt = 0; mt < 4; ++mt)
                ldsm4(a[mt],
                      ab + ((warp_m * 64 + mt * 16 + lrow) * PJ_LDH + s * 16 + lcolh) * 2);
#pragma unroll
            for (int mt = 0; mt < 4; ++mt)
#pragma unroll
                for (int p = 0; p < 2; ++p) {
                    mma16(acc[mt][2 * p],     a[mt], bf[p][0], bf[p][1]);
                    mma16(acc[mt][2 * p + 1], a[mt], bf[p][2], bf[p][3]);
                }
        }
    }

    // epilogue: bias + store (row -> (b, q))
#pragma unroll
    for (int mt = 0; mt < 4; ++mt)
#pragma unroll
        for (int nt = 0; nt < 4; ++nt) {
            int gr = m0 + warp_m * 64 + mt * 16 + grp;
            int o  = o0 + warp_n * 32 + nt * 8 + 2 * qd;
            float bv0 = bias[o], bv1 = bias[o + 1];
            int b0i = gr >> 6, q0 = gr & 63;
            int b1i = (gr + 8) >> 6, q1 = (gr + 8) & 63;
            float2 v0 = make_float2(acc[mt][nt][0] + bv0, acc[mt][nt][1] + bv1);
            float2 v1 = make_float2(acc[mt][nt][2] + bv0, acc[mt][nt][3] + bv1);
            *(float2*)&out[(size_t)b0i * NTOK * CDIM + (size_t)q0 * CDIM + o] = v0;
            *(float2*)&out[(size_t)b1i * NTOK * CDIM + (size_t)q1 * CDIM + o] = v1;
        }
}

extern "C" void kernel_launch(void* const* d_in, const int* in_sizes, int n_in,
                              void* d_out, int out_size) {
    const float* x    = (const float*)d_in[0];
    const float* w    = (const float*)d_in[1];
    const float* bias = (const float*)d_in[2];
    float* out = (float*)d_out;

    conv_k<<<2048, 256>>>((const float4*)x, (const float4*)w, (float4*)out);

    cudaFuncSetAttribute(attn_k, cudaFuncAttributeMaxDynamicSharedMemorySize, AT_SMEM);
    attn_k<<<BATCH, 256, AT_SMEM>>>();

    cudaFuncSetAttribute(proj_k, cudaFuncAttributeMaxDynamicSharedMemorySize, PJ_SMEM);
    proj_k<<<dim3(6, 128), 256, PJ_SMEM>>>(bias, out);
}